// round 9
// baseline (speedup 1.0000x reference)
#include <cuda_runtime.h>
#include <cuda_bf16.h>
#include <cstdint>

#define SAMP_BLOCKS 64
#define TPB         256

// Device-global scratch (no allocations). g_spart fully rewritten by K1 each
// launch; g_act_rng reset by K1 (stream-ordered before K2) -> deterministic.
__device__ unsigned g_spart[SAMP_BLOCKS];
__device__ unsigned g_act_rng;

// ---------------------------------------------------------------------------
// Robust small-integer scalar decode (int32/int64/float32/float64).
// ---------------------------------------------------------------------------
__device__ __forceinline__ int decode_scalar(const int* p, int dflt) {
    if (p == nullptr) return dflt;
    int w0 = p[0];
    if (w0 >= -1000000 && w0 <= 1000000) {
        if (w0 != 0) return w0;
        int w1 = p[1];
        if (w1 == 0) return 0;
        double d = __hiloint2double(w1, w0);
        if (d >= -1e6 && d <= 1e6) return (int)d;
        return 0;
    }
    float f = __int_as_float(w0);
    if (f >= -1e6f && f <= 1e6f) return (int)f;
    int w1 = p[1];
    double d = __hiloint2double(w1, w0);
    if (d >= -1e6 && d <= 1e6) return (int)d;
    return dflt;
}

// ---------------------------------------------------------------------------
// Transform descriptor: pack = mode | (shift << 2)
//   mode 0 = zeros (bw==0), 1 = int8-wrap trunc (shift<1), 2 = psto(shift)
// ---------------------------------------------------------------------------
__device__ __forceinline__ unsigned make_pack(unsigned rng, int mu) {
    if (rng == 0u) return 0u;
    int bw = (int)ceilf(log2f(fmaxf((float)rng, 1.0f)));
    int shift = bw - mu;
    if (shift < 1) return 1u;
    return 2u | ((unsigned)shift << 2);
}

// ---------------------------------------------------------------------------
// Pseudo-stochastic shift quantizer (bit-exact vs reference, s >= 1).
// ---------------------------------------------------------------------------
__device__ __forceinline__ int uw_psto(int x, int s) {
    int rt   = x >> s;
    int prob = x & ((1 << s) - 1);
    int hs   = s >> 1;
    int qprob = prob >> hs;
    int prn   = (prob & ((1 << hs) - 1)) * (1 + (s & 1));
    int sgn   = (x > 0) - (x < 0);
    int dec   = (qprob <= prn) ? 0 : sgn;
    return min(127, max(-127, rt + dec));
}

__device__ __forceinline__ unsigned max4abs(int4 v) {
    unsigned a0 = (unsigned)(v.x < 0 ? -v.x : v.x);
    unsigned a1 = (unsigned)(v.y < 0 ? -v.y : v.y);
    unsigned a2 = (unsigned)(v.z < 0 ? -v.z : v.z);
    unsigned a3 = (unsigned)(v.w < 0 ? -v.w : v.w);
    return max(max(a0, a1), max(a2, a3));
}

__device__ __forceinline__ void uw_apply(int4 gv, int4 wv, int mode, int s,
                                         float4& ow, float4& og) {
    int gx[4] = { gv.x, gv.y, gv.z, gv.w };
    int wi[4] = { wv.x, wv.y, wv.z, wv.w };
    float o_g[4], o_w[4];
#pragma unroll
    for (int k = 0; k < 4; k++) {
        int gq;
        if (mode == 0)      gq = 0;
        else if (mode == 1) gq = (int)(signed char)gx[k];   // wraps like astype(int8)
        else                gq = uw_psto(gx[k], s);
        int nw = wi[k] - gq;
        nw = min(127, max(-127, nw));
        o_g[k] = (float)gq;
        o_w[k] = (float)nw;
    }
    ow = make_float4(o_w[0], o_w[1], o_w[2], o_w[3]);
    og = make_float4(o_g[0], o_g[1], o_g[2], o_g[3]);
}

__device__ __forceinline__ unsigned block_reduce_max256(unsigned m, unsigned* s_red) {
    m = __reduce_max_sync(0xffffffffu, m);
    int lane = threadIdx.x & 31;
    int wid  = threadIdx.x >> 5;
    if (lane == 0) s_red[wid] = m;
    __syncthreads();
    unsigned v = 0u;
    if (wid == 0) {
        v = (lane < (int)(blockDim.x >> 5)) ? s_red[lane] : 0u;
        v = __reduce_max_sync(0xffffffffu, v);
    }
    return v;  // valid in warp 0
}

// Guess pack from g_spart (identical in every block -> deterministic).
// Uses threads 0..63 of warp 0+1 via block reduce; broadcast through smem.
__device__ __forceinline__ unsigned guess_from_spart(int mu, unsigned* s_red,
                                                     unsigned* s_bcast) {
    unsigned m = (threadIdx.x < SAMP_BLOCKS) ? g_spart[threadIdx.x] : 0u;
    unsigned r = block_reduce_max256(m, s_red);
    if (threadIdx.x == 0) *s_bcast = make_pack(r, mu);
    __syncthreads();
    return *s_bcast;
}

// ---------------------------------------------------------------------------
// K1: strided subsample of |grad| -> g_spart[block]; block 0 also resets
// g_act_rng for this launch (stream order puts this before K2).
// ---------------------------------------------------------------------------
__global__ void uw_sample_kernel(const int4* __restrict__ g, long n4, long st) {
    __shared__ unsigned s_red[32];
    if (blockIdx.x == 0 && threadIdx.x == 0) g_act_rng = 0u;
    long gid = (long)blockIdx.x * blockDim.x + threadIdx.x;
    unsigned m = 0u;
#pragma unroll
    for (int k = 0; k < 4; k++) {
        long idx = (gid * 4 + k) * st;
        if (idx < n4) m = max(m, max4abs(__ldg(&g[idx])));
    }
    unsigned bm = block_reduce_max256(m, s_red);
    if (threadIdx.x == 0) g_spart[blockIdx.x] = bm;
}

// ---------------------------------------------------------------------------
// K2: fused main pass, flat grid (1 int4/thread — R4's proven 6.45TB/s shape).
// Each block: computes guess from g_spart, transforms its slice with the
// guessed pack, and publishes its true max via one atomicMax.
// ---------------------------------------------------------------------------
__global__ void uw_main_kernel(
    const int4* __restrict__ w4,
    const int4* __restrict__ g4,
    float4* __restrict__ ow4,
    float4* __restrict__ og4,
    const int* __restrict__ p_mu,
    long n4)
{
    __shared__ unsigned s_red[32];
    __shared__ unsigned s_bcast;

    int mu = decode_scalar(p_mu, 7);
    unsigned pack = guess_from_spart(mu, s_red, &s_bcast);
    int mode = (int)(pack & 3u);
    int s    = (int)(pack >> 2);

    long i = (long)blockIdx.x * blockDim.x + threadIdx.x;
    unsigned m = 0u;
    if (i < n4) {
        int4 gv = __ldg(&g4[i]);
        int4 wv = __ldg(&w4[i]);
        m = max4abs(gv);
        float4 ow, og;
        uw_apply(gv, wv, mode, s, ow, og);
        ow4[i] = ow;
        og4[i] = og;
    }
    __syncthreads();   // s_red reuse
    unsigned bm = block_reduce_max256(m, s_red);
    if (threadIdx.x == 0) atomicMax(&g_act_rng, bm);
}

// ---------------------------------------------------------------------------
// K3: fixup. Recomputes guess (bit-identical) and actual pack; if equal,
// all blocks exit immediately (block 0 writes grad_exp). Otherwise rewrites
// all outputs with the actual transform -> always exactly correct.
// ---------------------------------------------------------------------------
__global__ void uw_fixup_kernel(
    const int4* __restrict__ w4,
    const int4* __restrict__ g4,
    float4* __restrict__ ow4,
    float4* __restrict__ og4,
    const int* __restrict__ p_err_exp,
    const int* __restrict__ p_act_in_exp,
    const int* __restrict__ p_mu,
    float* __restrict__ out_exp,
    long n4)
{
    __shared__ unsigned s_red[32];
    __shared__ unsigned s_bcast;

    int mu = decode_scalar(p_mu, 7);
    unsigned guess = guess_from_spart(mu, s_red, &s_bcast);
    unsigned actual = make_pack(g_act_rng, mu);

    if (blockIdx.x == 0 && threadIdx.x == 0) {
        int mode = (int)(actual & 3u);
        int gs   = (mode == 2) ? (int)(actual >> 2) : 0;
        int ee = decode_scalar(p_err_exp, -10);
        int ae = decode_scalar(p_act_in_exp, -7);
        *out_exp = (float)(ee + gs + ae);
    }
    if (actual == guess) return;   // overwhelmingly common path

    int mode = (int)(actual & 3u);
    int s    = (int)(actual >> 2);
    long i0     = (long)blockIdx.x * blockDim.x + threadIdx.x;
    long stride = (long)gridDim.x * blockDim.x;
    for (long i = i0; i < n4; i += stride) {
        int4 gv = __ldg(&g4[i]);
        int4 wv = __ldg(&w4[i]);
        float4 ow, og;
        uw_apply(gv, wv, mode, s, ow, og);
        ow4[i] = ow;
        og4[i] = og;
    }
}

// ---------------------------------------------------------------------------
// Launch. Inputs: weight int32[N] (promoted int8), grad int32[N],
// err_exp, act_in_exp, mu (int32 scalars).
// Output: float32[2N+1] = concat(new_weight, grad, grad_exp).
// ---------------------------------------------------------------------------
extern "C" void kernel_launch(void* const* d_in, const int* in_sizes, int n_in,
                              void* d_out, int out_size)
{
    const int4* w4 = (const int4*)d_in[0];
    const int4* g4 = (const int4*)d_in[1];
    const int* p_err = (n_in > 2) ? (const int*)d_in[2] : nullptr;
    const int* p_act = (n_in > 3) ? (const int*)d_in[3] : nullptr;
    const int* p_mu  = (n_in > 4) ? (const int*)d_in[4] : nullptr;

    long N  = (long)in_sizes[0];
    long n4 = N >> 2;

    float* out   = (float*)d_out;
    float4* ow4  = (float4*)out;
    float4* og4  = (float4*)(out + N);
    float* out_e = out + 2 * N;

    long st = n4 / ((long)SAMP_BLOCKS * 256 * 4);
    if (st < 1) st = 1;

    long mblocks = (n4 + TPB - 1) / TPB;

    uw_sample_kernel<<<SAMP_BLOCKS, TPB>>>(g4, n4, st);
    uw_main_kernel<<<(int)mblocks, TPB>>>(w4, g4, ow4, og4, p_mu, n4);
    uw_fixup_kernel<<<1184, TPB>>>(w4, g4, ow4, og4,
                                   p_err, p_act, p_mu, out_e, n4);
}

// round 10
// speedup vs baseline: 1.2672x; 1.2672x over previous
#include <cuda_runtime.h>
#include <cuda_bf16.h>
#include <cstdint>

#define SAMP_BLOCKS 64
#define MAIN_BLOCKS 1184
#define TPB         256

// Device-global scratch (no allocations). Counters self-reset every launch;
// all other cells are rewritten before being read -> deterministic.
__device__ unsigned g_spart[SAMP_BLOCKS];
__device__ unsigned g_guess_pack;
__device__ unsigned g_partial[MAIN_BLOCKS];
__device__ unsigned g_act_pack;
__device__ unsigned g_mismatch;
__device__ unsigned g_scnt;
__device__ unsigned g_mcnt;

// ---------------------------------------------------------------------------
// Robust small-integer scalar decode (int32/int64/float32/float64).
// ---------------------------------------------------------------------------
__device__ __forceinline__ int decode_scalar(const int* p, int dflt) {
    if (p == nullptr) return dflt;
    int w0 = p[0];
    if (w0 >= -1000000 && w0 <= 1000000) {
        if (w0 != 0) return w0;
        int w1 = p[1];
        if (w1 == 0) return 0;
        double d = __hiloint2double(w1, w0);
        if (d >= -1e6 && d <= 1e6) return (int)d;
        return 0;
    }
    float f = __int_as_float(w0);
    if (f >= -1e6f && f <= 1e6f) return (int)f;
    int w1 = p[1];
    double d = __hiloint2double(w1, w0);
    if (d >= -1e6 && d <= 1e6) return (int)d;
    return dflt;
}

// Transform descriptor: pack = mode | (shift << 2)
//   mode 0 = zeros (bw==0), 1 = int8-wrap trunc (shift<1), 2 = psto(shift)
__device__ __forceinline__ unsigned make_pack(unsigned rng, int mu) {
    if (rng == 0u) return 0u;
    int bw = (int)ceilf(log2f(fmaxf((float)rng, 1.0f)));
    int shift = bw - mu;
    if (shift < 1) return 1u;
    return 2u | ((unsigned)shift << 2);
}

// Pseudo-stochastic shift quantizer (bit-exact vs reference, s >= 1).
__device__ __forceinline__ int uw_psto(int x, int s) {
    int rt   = x >> s;
    int prob = x & ((1 << s) - 1);
    int hs   = s >> 1;
    int qprob = prob >> hs;
    int prn   = (prob & ((1 << hs) - 1)) * (1 + (s & 1));
    int sgn   = (x > 0) - (x < 0);
    int dec   = (qprob <= prn) ? 0 : sgn;
    return min(127, max(-127, rt + dec));
}

__device__ __forceinline__ unsigned max4abs(int4 v) {
    unsigned a0 = (unsigned)(v.x < 0 ? -v.x : v.x);
    unsigned a1 = (unsigned)(v.y < 0 ? -v.y : v.y);
    unsigned a2 = (unsigned)(v.z < 0 ? -v.z : v.z);
    unsigned a3 = (unsigned)(v.w < 0 ? -v.w : v.w);
    return max(max(a0, a1), max(a2, a3));
}

__device__ __forceinline__ void uw_apply(int4 gv, int4 wv, int mode, int s,
                                         float4& ow, float4& og) {
    int gx[4] = { gv.x, gv.y, gv.z, gv.w };
    int wi[4] = { wv.x, wv.y, wv.z, wv.w };
    float o_g[4], o_w[4];
#pragma unroll
    for (int k = 0; k < 4; k++) {
        int gq;
        if (mode == 0)      gq = 0;
        else if (mode == 1) gq = (int)(signed char)gx[k];   // wraps like astype(int8)
        else                gq = uw_psto(gx[k], s);
        int nw = wi[k] - gq;
        nw = min(127, max(-127, nw));
        o_g[k] = (float)gq;
        o_w[k] = (float)nw;
    }
    ow = make_float4(o_w[0], o_w[1], o_w[2], o_w[3]);
    og = make_float4(o_g[0], o_g[1], o_g[2], o_g[3]);
}

__device__ __forceinline__ unsigned block_reduce_max256(unsigned m, unsigned* s_red) {
    m = __reduce_max_sync(0xffffffffu, m);
    int lane = threadIdx.x & 31;
    int wid  = threadIdx.x >> 5;
    if (lane == 0) s_red[wid] = m;
    __syncthreads();
    unsigned v = 0u;
    if (wid == 0) {
        v = (lane < (int)(blockDim.x >> 5)) ? s_red[lane] : 0u;
        v = __reduce_max_sync(0xffffffffu, v);
    }
    return v;  // valid in warp 0
}

// ---------------------------------------------------------------------------
// K1: strided subsample of |grad| -> g_spart[block]; the LAST finishing block
// reduces g_spart -> g_guess_pack (and self-resets the counter).
// ---------------------------------------------------------------------------
__global__ void uw_sample_kernel(const int4* __restrict__ g, long n4, long st,
                                 const int* __restrict__ p_mu) {
    __shared__ unsigned s_red[32];
    __shared__ unsigned s_last;
    long gid = (long)blockIdx.x * blockDim.x + threadIdx.x;
    unsigned m = 0u;
#pragma unroll
    for (int k = 0; k < 4; k++) {
        long idx = (gid * 4 + k) * st;
        if (idx < n4) m = max(m, max4abs(__ldg(&g[idx])));
    }
    unsigned bm = block_reduce_max256(m, s_red);
    if (threadIdx.x == 0) {
        g_spart[blockIdx.x] = bm;
        __threadfence();
        unsigned t = atomicAdd(&g_scnt, 1u);
        s_last = (t == (unsigned)(gridDim.x - 1)) ? 1u : 0u;
    }
    __syncthreads();
    if (s_last) {
        unsigned v = (threadIdx.x < SAMP_BLOCKS) ? __ldcg(&g_spart[threadIdx.x]) : 0u;
        __syncthreads();                       // s_red reuse
        unsigned rng = block_reduce_max256(v, s_red);
        if (threadIdx.x == 0) {
            g_guess_pack = make_pack(rng, decode_scalar(p_mu, 7));
            g_scnt = 0u;                        // self-reset for next launch
        }
    }
}

// ---------------------------------------------------------------------------
// K2: fused main pass, grid-stride (MAIN_BLOCKS), manual 4-way batched loads
// for MLP. Writes outputs with the GUESSED transform; true per-block max ->
// g_partial. The LAST finishing block reduces partials -> actual pack,
// mismatch flag, grad_exp (and self-resets the counter).
// ---------------------------------------------------------------------------
__global__ void uw_main_kernel(
    const int4* __restrict__ w4,
    const int4* __restrict__ g4,
    float4* __restrict__ ow4,
    float4* __restrict__ og4,
    const int* __restrict__ p_err_exp,
    const int* __restrict__ p_act_in_exp,
    const int* __restrict__ p_mu,
    float* __restrict__ out_exp,
    long n4)
{
    __shared__ unsigned s_red[32];
    __shared__ unsigned s_last;

    unsigned pack = g_guess_pack;
    int mode = (int)(pack & 3u);
    int s    = (int)(pack >> 2);

    const long S  = (long)gridDim.x * blockDim.x;
    long i = (long)blockIdx.x * blockDim.x + threadIdx.x;

    unsigned m = 0u;
    // 4-way batched: 8 independent loads in flight per iteration.
    for (; i + 3 * S < n4; i += 4 * S) {
        int4 g0 = __ldg(&g4[i]);
        int4 g1 = __ldg(&g4[i +     S]);
        int4 g2 = __ldg(&g4[i + 2 * S]);
        int4 g3 = __ldg(&g4[i + 3 * S]);
        int4 w0 = __ldg(&w4[i]);
        int4 w1 = __ldg(&w4[i +     S]);
        int4 w2 = __ldg(&w4[i + 2 * S]);
        int4 w3 = __ldg(&w4[i + 3 * S]);
        m = max(m, max(max(max4abs(g0), max4abs(g1)),
                       max(max4abs(g2), max4abs(g3))));
        float4 ow, og;
        uw_apply(g0, w0, mode, s, ow, og); ow4[i]         = ow; og4[i]         = og;
        uw_apply(g1, w1, mode, s, ow, og); ow4[i +     S] = ow; og4[i +     S] = og;
        uw_apply(g2, w2, mode, s, ow, og); ow4[i + 2 * S] = ow; og4[i + 2 * S] = og;
        uw_apply(g3, w3, mode, s, ow, og); ow4[i + 3 * S] = ow; og4[i + 3 * S] = og;
    }
    for (; i < n4; i += S) {
        int4 gv = __ldg(&g4[i]);
        int4 wv = __ldg(&w4[i]);
        m = max(m, max4abs(gv));
        float4 ow, og;
        uw_apply(gv, wv, mode, s, ow, og);
        ow4[i] = ow;
        og4[i] = og;
    }

    unsigned bm = block_reduce_max256(m, s_red);
    if (threadIdx.x == 0) {
        g_partial[blockIdx.x] = bm;
        __threadfence();
        unsigned t = atomicAdd(&g_mcnt, 1u);
        s_last = (t == (unsigned)(gridDim.x - 1)) ? 1u : 0u;
    }
    __syncthreads();
    if (s_last) {
        unsigned m0 = 0u, m1 = 0u, m2 = 0u, m3 = 0u;
        for (int j = threadIdx.x * 4; j < MAIN_BLOCKS; j += blockDim.x * 4) {
            m0 = max(m0, __ldcg(&g_partial[j]));
            if (j + 1 < MAIN_BLOCKS) m1 = max(m1, __ldcg(&g_partial[j + 1]));
            if (j + 2 < MAIN_BLOCKS) m2 = max(m2, __ldcg(&g_partial[j + 2]));
            if (j + 3 < MAIN_BLOCKS) m3 = max(m3, __ldcg(&g_partial[j + 3]));
        }
        unsigned mm = max(max(m0, m1), max(m2, m3));
        __syncthreads();                       // s_red reuse
        unsigned rng = block_reduce_max256(mm, s_red);
        if (threadIdx.x == 0) {
            int mu = decode_scalar(p_mu, 7);
            unsigned act = make_pack(rng, mu);
            g_act_pack = act;
            g_mismatch = (act != pack) ? 1u : 0u;
            int amode = (int)(act & 3u);
            int gs    = (amode == 2) ? (int)(act >> 2) : 0;
            int ee = decode_scalar(p_err_exp, -10);
            int ae = decode_scalar(p_act_in_exp, -7);
            *out_exp = (float)(ee + gs + ae);
            g_mcnt = 0u;                        // self-reset for next launch
        }
    }
}

// ---------------------------------------------------------------------------
// K3: fixup. If the guess matched (overwhelmingly likely), every block exits
// immediately. Otherwise rewrites all outputs with the actual transform.
// ---------------------------------------------------------------------------
__global__ void uw_fixup_kernel(
    const int4* __restrict__ w4,
    const int4* __restrict__ g4,
    float4* __restrict__ ow4,
    float4* __restrict__ og4,
    long n4)
{
    if (g_mismatch == 0u) return;
    unsigned pack = g_act_pack;
    int mode = (int)(pack & 3u);
    int s    = (int)(pack >> 2);

    long i0     = (long)blockIdx.x * blockDim.x + threadIdx.x;
    long stride = (long)gridDim.x * blockDim.x;
    for (long i = i0; i < n4; i += stride) {
        int4 gv = __ldg(&g4[i]);
        int4 wv = __ldg(&w4[i]);
        float4 ow, og;
        uw_apply(gv, wv, mode, s, ow, og);
        ow4[i] = ow;
        og4[i] = og;
    }
}

// ---------------------------------------------------------------------------
// Launch. Inputs: weight int32[N] (promoted int8), grad int32[N],
// err_exp, act_in_exp, mu (int32 scalars).
// Output: float32[2N+1] = concat(new_weight, grad, grad_exp).
// ---------------------------------------------------------------------------
extern "C" void kernel_launch(void* const* d_in, const int* in_sizes, int n_in,
                              void* d_out, int out_size)
{
    const int4* w4 = (const int4*)d_in[0];
    const int4* g4 = (const int4*)d_in[1];
    const int* p_err = (n_in > 2) ? (const int*)d_in[2] : nullptr;
    const int* p_act = (n_in > 3) ? (const int*)d_in[3] : nullptr;
    const int* p_mu  = (n_in > 4) ? (const int*)d_in[4] : nullptr;

    long N  = (long)in_sizes[0];
    long n4 = N >> 2;

    float* out   = (float*)d_out;
    float4* ow4  = (float4*)out;
    float4* og4  = (float4*)(out + N);
    float* out_e = out + 2 * N;

    long st = n4 / ((long)SAMP_BLOCKS * 256 * 4);
    if (st < 1) st = 1;

    uw_sample_kernel<<<SAMP_BLOCKS, TPB>>>(g4, n4, st, p_mu);
    uw_main_kernel<<<MAIN_BLOCKS, TPB>>>(w4, g4, ow4, og4,
                                         p_err, p_act, p_mu, out_e, n4);
    uw_fixup_kernel<<<MAIN_BLOCKS, TPB>>>(w4, g4, ow4, og4, n4);
}

// round 11
// speedup vs baseline: 1.2775x; 1.0081x over previous
#include <cuda_runtime.h>
#include <cuda_bf16.h>
#include <cstdint>

#define SAMP_BLOCKS 64
#define SAMP_PER_T  4          // int4 per thread, contiguous within chunk
#define MAIN_BLOCKS 1184
#define TPB         256

// Device-global scratch (no allocations). Counters self-reset every launch;
// all other cells are rewritten before being read -> deterministic.
__device__ unsigned g_spart[SAMP_BLOCKS];
__device__ unsigned g_guess_pack;
__device__ unsigned g_partial[MAIN_BLOCKS];
__device__ unsigned g_act_pack;
__device__ unsigned g_mismatch;
__device__ unsigned g_scnt;
__device__ unsigned g_mcnt;

// ---------------------------------------------------------------------------
// Robust small-integer scalar decode (int32/int64/float32/float64).
// ---------------------------------------------------------------------------
__device__ __forceinline__ int decode_scalar(const int* p, int dflt) {
    if (p == nullptr) return dflt;
    int w0 = p[0];
    if (w0 >= -1000000 && w0 <= 1000000) {
        if (w0 != 0) return w0;
        int w1 = p[1];
        if (w1 == 0) return 0;
        double d = __hiloint2double(w1, w0);
        if (d >= -1e6 && d <= 1e6) return (int)d;
        return 0;
    }
    float f = __int_as_float(w0);
    if (f >= -1e6f && f <= 1e6f) return (int)f;
    int w1 = p[1];
    double d = __hiloint2double(w1, w0);
    if (d >= -1e6 && d <= 1e6) return (int)d;
    return dflt;
}

// Transform descriptor: pack = mode | (shift << 2)
//   mode 0 = zeros (bw==0), 1 = int8-wrap trunc (shift<1), 2 = psto(shift)
__device__ __forceinline__ unsigned make_pack(unsigned rng, int mu) {
    if (rng == 0u) return 0u;
    int bw = (int)ceilf(log2f(fmaxf((float)rng, 1.0f)));
    int shift = bw - mu;
    if (shift < 1) return 1u;
    return 2u | ((unsigned)shift << 2);
}

// Pseudo-stochastic shift quantizer (bit-exact vs reference, s >= 1).
__device__ __forceinline__ int uw_psto(int x, int s) {
    int rt   = x >> s;
    int prob = x & ((1 << s) - 1);
    int hs   = s >> 1;
    int qprob = prob >> hs;
    int prn   = (prob & ((1 << hs) - 1)) * (1 + (s & 1));
    int sgn   = (x > 0) - (x < 0);
    int dec   = (qprob <= prn) ? 0 : sgn;
    return min(127, max(-127, rt + dec));
}

__device__ __forceinline__ unsigned max4abs(int4 v) {
    unsigned a0 = (unsigned)(v.x < 0 ? -v.x : v.x);
    unsigned a1 = (unsigned)(v.y < 0 ? -v.y : v.y);
    unsigned a2 = (unsigned)(v.z < 0 ? -v.z : v.z);
    unsigned a3 = (unsigned)(v.w < 0 ? -v.w : v.w);
    return max(max(a0, a1), max(a2, a3));
}

__device__ __forceinline__ void uw_apply(int4 gv, int4 wv, int mode, int s,
                                         float4& ow, float4& og) {
    int gx[4] = { gv.x, gv.y, gv.z, gv.w };
    int wi[4] = { wv.x, wv.y, wv.z, wv.w };
    float o_g[4], o_w[4];
#pragma unroll
    for (int k = 0; k < 4; k++) {
        int gq;
        if (mode == 0)      gq = 0;
        else if (mode == 1) gq = (int)(signed char)gx[k];   // wraps like astype(int8)
        else                gq = uw_psto(gx[k], s);
        int nw = wi[k] - gq;
        nw = min(127, max(-127, nw));
        o_g[k] = (float)gq;
        o_w[k] = (float)nw;
    }
    ow = make_float4(o_w[0], o_w[1], o_w[2], o_w[3]);
    og = make_float4(o_g[0], o_g[1], o_g[2], o_g[3]);
}

__device__ __forceinline__ unsigned block_reduce_max256(unsigned m, unsigned* s_red) {
    m = __reduce_max_sync(0xffffffffu, m);
    int lane = threadIdx.x & 31;
    int wid  = threadIdx.x >> 5;
    if (lane == 0) s_red[wid] = m;
    __syncthreads();
    unsigned v = 0u;
    if (wid == 0) {
        v = (lane < (int)(blockDim.x >> 5)) ? s_red[lane] : 0u;
        v = __reduce_max_sync(0xffffffffu, v);
    }
    return v;  // valid in warp 0
}

// ---------------------------------------------------------------------------
// K1: COALESCED chunk sampling. Each block reads a contiguous 16KB chunk
// (SAMP_PER_T int4 per thread) at an evenly spaced offset -> 64 chunks span
// the array. Last finishing block reduces g_spart -> g_guess_pack.
// ---------------------------------------------------------------------------
__global__ void uw_sample_kernel(const int4* __restrict__ g, long n4,
                                 long chunk_stride,
                                 const int* __restrict__ p_mu) {
    __shared__ unsigned s_red[32];
    __shared__ unsigned s_last;
    long base = (long)blockIdx.x * chunk_stride;
    unsigned m = 0u;
#pragma unroll
    for (int k = 0; k < SAMP_PER_T; k++) {
        long idx = base + (long)k * blockDim.x + threadIdx.x;   // coalesced
        if (idx < n4) m = max(m, max4abs(__ldg(&g[idx])));
    }
    unsigned bm = block_reduce_max256(m, s_red);
    if (threadIdx.x == 0) {
        g_spart[blockIdx.x] = bm;
        __threadfence();
        unsigned t = atomicAdd(&g_scnt, 1u);
        s_last = (t == (unsigned)(gridDim.x - 1)) ? 1u : 0u;
    }
    __syncthreads();
    if (s_last) {
        unsigned v = (threadIdx.x < SAMP_BLOCKS) ? __ldcg(&g_spart[threadIdx.x]) : 0u;
        __syncthreads();                       // s_red reuse
        unsigned rng = block_reduce_max256(v, s_red);
        if (threadIdx.x == 0) {
            g_guess_pack = make_pack(rng, decode_scalar(p_mu, 7));
            g_scnt = 0u;                        // self-reset for next launch
        }
    }
}

// ---------------------------------------------------------------------------
// K2: fused main pass, grid-stride (MAIN_BLOCKS), 4-way batched loads for
// MLP. Writes outputs with the GUESSED transform; true per-block max ->
// g_partial. Last finishing block reduces partials -> actual pack, mismatch
// flag, grad_exp.
// ---------------------------------------------------------------------------
__global__ void uw_main_kernel(
    const int4* __restrict__ w4,
    const int4* __restrict__ g4,
    float4* __restrict__ ow4,
    float4* __restrict__ og4,
    const int* __restrict__ p_err_exp,
    const int* __restrict__ p_act_in_exp,
    const int* __restrict__ p_mu,
    float* __restrict__ out_exp,
    long n4)
{
    __shared__ unsigned s_red[32];
    __shared__ unsigned s_last;

    unsigned pack = g_guess_pack;
    int mode = (int)(pack & 3u);
    int s    = (int)(pack >> 2);

    const long S  = (long)gridDim.x * blockDim.x;
    long i = (long)blockIdx.x * blockDim.x + threadIdx.x;

    unsigned m = 0u;
    // 4-way batched: 8 independent loads in flight per iteration.
    for (; i + 3 * S < n4; i += 4 * S) {
        int4 g0 = __ldg(&g4[i]);
        int4 g1 = __ldg(&g4[i +     S]);
        int4 g2 = __ldg(&g4[i + 2 * S]);
        int4 g3 = __ldg(&g4[i + 3 * S]);
        int4 w0 = __ldg(&w4[i]);
        int4 w1 = __ldg(&w4[i +     S]);
        int4 w2 = __ldg(&w4[i + 2 * S]);
        int4 w3 = __ldg(&w4[i + 3 * S]);
        m = max(m, max(max(max4abs(g0), max4abs(g1)),
                       max(max4abs(g2), max4abs(g3))));
        float4 ow, og;
        uw_apply(g0, w0, mode, s, ow, og); ow4[i]         = ow; og4[i]         = og;
        uw_apply(g1, w1, mode, s, ow, og); ow4[i +     S] = ow; og4[i +     S] = og;
        uw_apply(g2, w2, mode, s, ow, og); ow4[i + 2 * S] = ow; og4[i + 2 * S] = og;
        uw_apply(g3, w3, mode, s, ow, og); ow4[i + 3 * S] = ow; og4[i + 3 * S] = og;
    }
    for (; i < n4; i += S) {
        int4 gv = __ldg(&g4[i]);
        int4 wv = __ldg(&w4[i]);
        m = max(m, max4abs(gv));
        float4 ow, og;
        uw_apply(gv, wv, mode, s, ow, og);
        ow4[i] = ow;
        og4[i] = og;
    }

    unsigned bm = block_reduce_max256(m, s_red);
    if (threadIdx.x == 0) {
        g_partial[blockIdx.x] = bm;
        __threadfence();
        unsigned t = atomicAdd(&g_mcnt, 1u);
        s_last = (t == (unsigned)(gridDim.x - 1)) ? 1u : 0u;
    }
    __syncthreads();
    if (s_last) {
        unsigned m0 = 0u, m1 = 0u, m2 = 0u, m3 = 0u;
        for (int j = threadIdx.x * 4; j < MAIN_BLOCKS; j += blockDim.x * 4) {
            m0 = max(m0, __ldcg(&g_partial[j]));
            if (j + 1 < MAIN_BLOCKS) m1 = max(m1, __ldcg(&g_partial[j + 1]));
            if (j + 2 < MAIN_BLOCKS) m2 = max(m2, __ldcg(&g_partial[j + 2]));
            if (j + 3 < MAIN_BLOCKS) m3 = max(m3, __ldcg(&g_partial[j + 3]));
        }
        unsigned mm = max(max(m0, m1), max(m2, m3));
        __syncthreads();                       // s_red reuse
        unsigned rng = block_reduce_max256(mm, s_red);
        if (threadIdx.x == 0) {
            int mu = decode_scalar(p_mu, 7);
            unsigned act = make_pack(rng, mu);
            g_act_pack = act;
            g_mismatch = (act != pack) ? 1u : 0u;
            int amode = (int)(act & 3u);
            int gs    = (amode == 2) ? (int)(act >> 2) : 0;
            int ee = decode_scalar(p_err_exp, -10);
            int ae = decode_scalar(p_act_in_exp, -7);
            *out_exp = (float)(ee + gs + ae);
            g_mcnt = 0u;                        // self-reset for next launch
        }
    }
}

// ---------------------------------------------------------------------------
// K3: fixup. If the guess matched (overwhelmingly likely), every block exits
// immediately. Otherwise rewrites all outputs with the actual transform.
// ---------------------------------------------------------------------------
__global__ void uw_fixup_kernel(
    const int4* __restrict__ w4,
    const int4* __restrict__ g4,
    float4* __restrict__ ow4,
    float4* __restrict__ og4,
    long n4)
{
    if (g_mismatch == 0u) return;
    unsigned pack = g_act_pack;
    int mode = (int)(pack & 3u);
    int s    = (int)(pack >> 2);

    long i0     = (long)blockIdx.x * blockDim.x + threadIdx.x;
    long stride = (long)gridDim.x * blockDim.x;
    for (long i = i0; i < n4; i += stride) {
        int4 gv = __ldg(&g4[i]);
        int4 wv = __ldg(&w4[i]);
        float4 ow, og;
        uw_apply(gv, wv, mode, s, ow, og);
        ow4[i] = ow;
        og4[i] = og;
    }
}

// ---------------------------------------------------------------------------
// Launch. Inputs: weight int32[N] (promoted int8), grad int32[N],
// err_exp, act_in_exp, mu (int32 scalars).
// Output: float32[2N+1] = concat(new_weight, grad, grad_exp).
// ---------------------------------------------------------------------------
extern "C" void kernel_launch(void* const* d_in, const int* in_sizes, int n_in,
                              void* d_out, int out_size)
{
    const int4* w4 = (const int4*)d_in[0];
    const int4* g4 = (const int4*)d_in[1];
    const int* p_err = (n_in > 2) ? (const int*)d_in[2] : nullptr;
    const int* p_act = (n_in > 3) ? (const int*)d_in[3] : nullptr;
    const int* p_mu  = (n_in > 4) ? (const int*)d_in[4] : nullptr;

    long N  = (long)in_sizes[0];
    long n4 = N >> 2;

    float* out   = (float*)d_out;
    float4* ow4  = (float4*)out;
    float4* og4  = (float4*)(out + N);
    float* out_e = out + 2 * N;

    // Evenly spaced contiguous chunks spanning the array.
    long chunk_stride = n4 / SAMP_BLOCKS;
    if (chunk_stride < TPB * SAMP_PER_T) chunk_stride = TPB * SAMP_PER_T;

    uw_sample_kernel<<<SAMP_BLOCKS, TPB>>>(g4, n4, chunk_stride, p_mu);
    uw_main_kernel<<<MAIN_BLOCKS, TPB>>>(w4, g4, ow4, og4,
                                         p_err, p_act, p_mu, out_e, n4);
    uw_fixup_kernel<<<MAIN_BLOCKS, TPB>>>(w4, g4, ow4, og4, n4);
}